// round 13
// baseline (speedup 1.0000x reference)
#include <cuda_runtime.h>
#include <cuda_bf16.h>
#include <cstdint>

#define NN 10000
#define DD 32
#define CL 8

// ---------------- device scratch (no allocation allowed) ----------------
__device__ float g_XW1[NN * 1024];    // node_feats @ Wih1^T
__device__ float g_gates[NN * 1024];  // XW2 scratch
__device__ float g_h1[NN * 256];
__device__ float g_hB[NN * 256];
__device__ float g_c1[NN * 256];
__device__ float g_hs[NN * 256];
__device__ __nv_bfloat16 g_W1h[1024 * 256];
__device__ __nv_bfloat16 g_W1l[1024 * 256];
__device__ float g_bsum[1024];
__device__ __nv_bfloat16 g_hhA[NN * 256];
__device__ __nv_bfloat16 g_hlA[NN * 256];
__device__ __nv_bfloat16 g_hhB[NN * 256];
__device__ __nv_bfloat16 g_hlB[NN * 256];

// ---------------- helpers ----------------
__device__ __forceinline__ unsigned long long pack2f(float x) {
    unsigned long long r;
    asm("mov.b64 %0, {%1, %1};" : "=l"(r) : "f"(x));
    return r;
}
__device__ __forceinline__ float2 unpack2f(unsigned long long v) {
    float2 r;
    asm("mov.b64 {%0, %1}, %2;" : "=f"(r.x), "=f"(r.y) : "l"(v));
    return r;
}
#define FMA2(acc, a, b) asm("fma.rn.f32x2 %0, %1, %2, %0;" : "+l"(acc) : "l"(a), "l"(b))

__device__ __forceinline__ float sigm(float x)   { return 1.f / (1.f + __expf(-x)); }
__device__ __forceinline__ float tanh_f(float x) { return 1.f - 2.f / (__expf(2.f * x) + 1.f); }

__device__ __forceinline__ uint32_t smem_u32(const void* p) {
    uint32_t a;
    asm("{ .reg .u64 t; cvta.to.shared.u64 t, %1; cvt.u32.u64 %0, t; }" : "=r"(a) : "l"(p));
    return a;
}
__device__ __forceinline__ uint32_t ctarank() {
    uint32_t r; asm("mov.u32 %0, %%cluster_ctarank;" : "=r"(r)); return r;
}

#define MBAR_INIT(addr, cnt) \
    asm volatile("mbarrier.init.shared.b64 [%0], %1;" :: "r"((uint32_t)(addr)), "r"((uint32_t)(cnt)) : "memory")

#define MBAR_ARM_TX(addr, tx) \
    asm volatile("mbarrier.arrive.expect_tx.shared.b64 _, [%0], %1;" :: "r"((uint32_t)(addr)), "r"((uint32_t)(tx)) : "memory")

#define MBAR_WAIT_CLUSTER(addr, ph) do {                                              \
    uint32_t _done = 0;                                                               \
    while (!_done) {                                                                  \
        asm volatile("{\n\t.reg .pred p;\n\t"                                         \
            "mbarrier.try_wait.parity.acquire.cluster.shared::cta.b64 p, [%1], %2;\n\t" \
            "selp.b32 %0, 1, 0, p;\n\t}"                                              \
            : "=r"(_done) : "r"((uint32_t)(addr)), "r"((uint32_t)(ph)) : "memory");   \
    }                                                                                 \
} while (0)

#define ST_ASYNC_F32(raddr, bits, rmbar) \
    asm volatile("st.async.weak.shared::cluster.mbarrier::complete_tx::bytes.b32 [%0], %1, [%2];" \
                 :: "r"(raddr), "r"(bits), "r"(rmbar) : "memory")

__device__ __forceinline__ void splitbf(float v, __nv_bfloat16& hi, __nv_bfloat16& lo) {
    hi = __float2bfloat16(v);
    lo = __float2bfloat16(v - __bfloat162float(hi));
}

// ---- mma.sync / ldmatrix / cp.async (portable sm_80+ path) ----
__device__ __forceinline__ void ldm_x4(uint32_t* r, uint32_t addr) {
    asm volatile("ldmatrix.sync.aligned.m8n8.x4.shared.b16 {%0,%1,%2,%3}, [%4];"
        : "=r"(r[0]), "=r"(r[1]), "=r"(r[2]), "=r"(r[3]) : "r"(addr));
}
__device__ __forceinline__ void ldm_x2(uint32_t* r, uint32_t addr) {
    asm volatile("ldmatrix.sync.aligned.m8n8.x2.shared.b16 {%0,%1}, [%2];"
        : "=r"(r[0]), "=r"(r[1]) : "r"(addr));
}
__device__ __forceinline__ void mma16816(float* d, const uint32_t* a, const uint32_t* b) {
    asm volatile(
        "mma.sync.aligned.m16n8k16.row.col.f32.bf16.bf16.f32 "
        "{%0,%1,%2,%3}, {%4,%5,%6,%7}, {%8,%9}, {%0,%1,%2,%3};"
        : "+f"(d[0]), "+f"(d[1]), "+f"(d[2]), "+f"(d[3])
        : "r"(a[0]), "r"(a[1]), "r"(a[2]), "r"(a[3]), "r"(b[0]), "r"(b[1]));
}
#define CP_ASYNC16(dst, src) \
    asm volatile("cp.async.cg.shared.global [%0], [%1], 16;" :: "r"(dst), "l"(src) : "memory")
#define CP_COMMIT() asm volatile("cp.async.commit_group;" ::: "memory")
#define CP_WAIT(n)  asm volatile("cp.async.wait_group %0;" :: "n"(n) : "memory")

// ================= FUSED HMMA step v3: 3-stage pipeline, 1 sync/kt =================
// gates = hh@Wh^T + hh@Wl^T + hl@Wh^T, K=256 in 16 k16-tiles, 3 smem stages.
// CTA: 64 rows x 128 cols (32 units x 4 gates). 8 warps = 2(M) x 4(N). Row stride 48B.
// dsm layout per stage (18432B): A: 2 x 64 x 48B (6144), B at +6144: 2 x 128 x 48B (12288)
#define STG_BYTES 18432
#define SMEM_FUSED (3 * STG_BYTES)
__global__ __launch_bounds__(256, 3) void fused_hmma_step(
    const __nv_bfloat16* __restrict__ hh, const __nv_bfloat16* __restrict__ hl,
    const float* __restrict__ XW1, const int* __restrict__ edges,
    const float* __restrict__ ew, int t,
    float* __restrict__ houtF, __nv_bfloat16* __restrict__ houth,
    __nv_bfloat16* __restrict__ houtl, float* __restrict__ cbuf)
{
    extern __shared__ __align__(16) char dsm[];
    uint32_t sb = smem_u32(dsm);

    int tid = threadIdx.x, wid = tid >> 5, lane = tid & 31;
    int wm = wid >> 2, nw = wid & 3;
    int u0 = blockIdx.x * 32;
    int rowBase = blockIdx.y * 64;

    // ldmatrix per-lane offsets (bytes), row stride 48B
    int q4 = lane >> 3;
    uint32_t aOff = (uint32_t)((wm * 32 + (q4 & 1) * 8 + (lane & 7)) * 48 + (q4 >> 1) * 16);
    int ql = lane & 15, q2 = ql >> 3;
    uint32_t bOff = (uint32_t)((nw * 8 + (ql & 7)) * 48 + q2 * 16);

    uint32_t aBase[3][2], bBase[3][2];
    #pragma unroll
    for (int b = 0; b < 3; b++)
        #pragma unroll
        for (int s = 0; s < 2; s++) {
            aBase[b][s] = sb + (uint32_t)(b * STG_BYTES + s * 3072) + aOff;
            bBase[b][s] = sb + (uint32_t)(b * STG_BYTES + 6144 + s * 6144) + bOff;
        }

    float acc[2][4][4];
    #pragma unroll
    for (int mt = 0; mt < 2; mt++)
        #pragma unroll
        for (int g = 0; g < 4; g++)
            #pragma unroll
            for (int e = 0; e < 4; e++) acc[mt][g][e] = 0.f;

    // cp.async loader: 768 x 16B chunks per k16 tile
#define H2_ISSUE(kt_, b_) do { \
    int k0_ = (kt_) * 16; \
    uint32_t stg_ = sb + (uint32_t)((b_) * STG_BYTES); \
    _Pragma("unroll") \
    for (int rep_ = 0; rep_ < 3; rep_++) { \
        int c_ = rep_ * 256 + tid; \
        int slot_ = c_ >> 1, half_ = c_ & 1; \
        uint32_t dst_; const __nv_bfloat16* src_; \
        if (slot_ < 128) { \
            int sel_ = slot_ >> 6, row_ = slot_ & 63; \
            int gr_ = rowBase + row_; if (gr_ >= NN) gr_ = NN - 1; \
            src_ = (sel_ ? hl : hh) + (size_t)gr_ * 256 + k0_ + half_ * 8; \
            dst_ = stg_ + (uint32_t)(sel_ * 3072 + row_ * 48 + half_ * 16); \
        } else { \
            int s2_ = slot_ - 128; \
            int sel_ = s2_ >> 7, j_ = s2_ & 127; \
            int wrow_ = (j_ >> 5) * 256 + u0 + (j_ & 31); \
            src_ = (sel_ ? g_W1l : g_W1h) + (size_t)wrow_ * 256 + k0_ + half_ * 8; \
            dst_ = stg_ + (uint32_t)(6144 + sel_ * 6144 + j_ * 48 + half_ * 16); \
        } \
        CP_ASYNC16(dst_, src_); \
    } \
    CP_COMMIT(); \
} while (0)

    H2_ISSUE(0, 0);
    H2_ISSUE(1, 1);

    #pragma unroll 1
    for (int kt = 0; kt < 16; kt++) {
        int buf = kt % 3;
        __syncthreads();   // all warps done reading stage (kt+2)%3 (used at kt-1)
        if (kt + 2 < 16) { H2_ISSUE(kt + 2, (kt + 2) % 3); CP_WAIT(2); }
        else if (kt + 1 < 16) { CP_WAIT(1); }
        else { CP_WAIT(0); }

        uint32_t ahh[2][4], ahl[2][4], bwh[4][2], bwl[4][2];
        #pragma unroll
        for (int mt = 0; mt < 2; mt++) {
            ldm_x4(ahh[mt], aBase[buf][0] + (uint32_t)(mt * 768));
            ldm_x4(ahl[mt], aBase[buf][1] + (uint32_t)(mt * 768));
        }
        #pragma unroll
        for (int g = 0; g < 4; g++) {
            ldm_x2(bwh[g], bBase[buf][0] + (uint32_t)(g * 1536));
            ldm_x2(bwl[g], bBase[buf][1] + (uint32_t)(g * 1536));
        }
        #pragma unroll
        for (int mt = 0; mt < 2; mt++)
            #pragma unroll
            for (int g = 0; g < 4; g++) {
                mma16816(acc[mt][g], ahh[mt], bwh[g]);
                mma16816(acc[mt][g], ahh[mt], bwl[g]);
                mma16816(acc[mt][g], ahl[mt], bwh[g]);
            }
    }

    // ---- epilogue: bias + gather + cell; d-frag rows lane>>2 (+8), unit pair (lane&3)*2 ----
    int uc = u0 + nw * 8 + (lane & 3) * 2;
    #pragma unroll
    for (int mt = 0; mt < 2; mt++) {
        #pragma unroll
        for (int half = 0; half < 2; half++) {
            int r = rowBase + wm * 32 + mt * 16 + (lane >> 2) + half * 8;
            if (r < NN) {
                int eI = edges[r * DD + t];
                float wgt = ew[r * DD + t];
                const float* xr = XW1 + (size_t)eI * 1024;
                float2 xi = *(const float2*)(xr + uc);
                float2 xf = *(const float2*)(xr + 256 + uc);
                float2 xg = *(const float2*)(xr + 512 + uc);
                float2 xo = *(const float2*)(xr + 768 + uc);
                float* cp = cbuf + (size_t)r * 256 + uc;
                float2 cc = *(float2*)cp;
                float hn[2];
                #pragma unroll
                for (int s = 0; s < 2; s++) {
                    int e = half * 2 + s;
                    float vi = acc[mt][0][e] + g_bsum[uc + s]       + wgt * (s ? xi.y : xi.x);
                    float vf = acc[mt][1][e] + g_bsum[256 + uc + s] + wgt * (s ? xf.y : xf.x);
                    float vg = acc[mt][2][e] + g_bsum[512 + uc + s] + wgt * (s ? xg.y : xg.x);
                    float vo = acc[mt][3][e] + g_bsum[768 + uc + s] + wgt * (s ? xo.y : xo.x);
                    float c2 = sigm(vf) * (s ? cc.y : cc.x) + sigm(vi) * tanh_f(vg);
                    if (s) cc.y = c2; else cc.x = c2;
                    hn[s] = sigm(vo) * tanh_f(c2);
                }
                *(float2*)cp = cc;
                *(float2*)(houtF + (size_t)r * 256 + uc) = make_float2(hn[0], hn[1]);
                __nv_bfloat16 a, al, b, bl;
                splitbf(hn[0], a, al);
                splitbf(hn[1], b, bl);
                *(__nv_bfloat162*)(houth + (size_t)r * 256 + uc) = __halves2bfloat162(a, b);
                *(__nv_bfloat162*)(houtl + (size_t)r * 256 + uc) = __halves2bfloat162(al, bl);
            }
        }
    }
}

// ---------------- one-time: split Whh1 into bf16 hi/lo + bias sum ----------------
__global__ void split_w_kernel(const float* __restrict__ Whh1,
                               const float* __restrict__ bih1, const float* __restrict__ bhh1)
{
    int idx = blockIdx.x * 256 + threadIdx.x;
    if (idx < 1024 * 256) {
        __nv_bfloat16 hi, lo;
        splitbf(Whh1[idx], hi, lo);
        g_W1h[idx] = hi;
        g_W1l[idx] = lo;
    }
    if (idx < 1024) g_bsum[idx] = bih1[idx] + bhh1[idx];
}

// ---------------- generic K=256 fp32 GEMM: C = A @ W^T (+b1+b2) ----------------
#define LOAD_AB(off) do { \
    if (aval) { ra0 = *(const float4*)(Arow + (off)); ra1 = *(const float4*)(Arow + (off) + 4); } \
    else      { ra0 = zf4; ra1 = zf4; } \
    rb0 = *(const float4*)(Wrow + (off)); rb1 = *(const float4*)(Wrow + (off) + 4); \
} while (0)

#define STORE_AB(buf) do { \
    As[buf][lc+0][lr]=ra0.x; As[buf][lc+1][lr]=ra0.y; As[buf][lc+2][lr]=ra0.z; As[buf][lc+3][lr]=ra0.w; \
    As[buf][lc+4][lr]=ra1.x; As[buf][lc+5][lr]=ra1.y; As[buf][lc+6][lr]=ra1.z; As[buf][lc+7][lr]=ra1.w; \
    Bs[buf][lc+0][lr]=rb0.x; Bs[buf][lc+1][lr]=rb0.y; Bs[buf][lc+2][lr]=rb0.z; Bs[buf][lc+3][lr]=rb0.w; \
    Bs[buf][lc+4][lr]=rb1.x; Bs[buf][lc+5][lr]=rb1.y; Bs[buf][lc+6][lr]=rb1.z; Bs[buf][lc+7][lr]=rb1.w; \
} while (0)

__global__ __launch_bounds__(256, 2) void gemm256_kernel(
    const float* __restrict__ A, const float* __restrict__ W,
    float* __restrict__ C, int M, int Nout,
    const float* __restrict__ b1, const float* __restrict__ b2)
{
    __shared__ __align__(16) float As[2][16][128];
    __shared__ __align__(16) float Bs[2][16][128];

    int tid = threadIdx.x;
    int rowBase = blockIdx.y * 128;
    int colBase = blockIdx.x * 128;

    int lr = tid >> 1;
    int lc = (tid & 1) * 8;
    int ar = rowBase + lr;
    const float* Arow = A + (size_t)ar * 256 + lc;
    const float* Wrow = W + (size_t)(colBase + lr) * 256 + lc;
    bool aval = (ar < M);
    float4 zf4 = make_float4(0.f, 0.f, 0.f, 0.f);

    int tm = (tid >> 4) * 8;
    int tn = (tid & 15) * 8;

    unsigned long long acc[8][4];
    #pragma unroll
    for (int i = 0; i < 8; i++)
        #pragma unroll
        for (int j = 0; j < 4; j++) acc[i][j] = 0ull;

    float4 ra0, ra1, rb0, rb1;
    LOAD_AB(0);
    STORE_AB(0);
    __syncthreads();

    #pragma unroll 1
    for (int kt = 0; kt < 16; kt++) {
        int buf = kt & 1;
        if (kt < 15) LOAD_AB((kt + 1) * 16);
        #pragma unroll
        for (int kk = 0; kk < 16; kk++) {
            float4 a0 = *(const float4*)&As[buf][kk][tm];
            float4 a1 = *(const float4*)&As[buf][kk][tm + 4];
            ulonglong2 bq0 = *(const ulonglong2*)&Bs[buf][kk][tn];
            ulonglong2 bq1 = *(const ulonglong2*)&Bs[buf][kk][tn + 4];
            float av[8] = {a0.x, a0.y, a0.z, a0.w, a1.x, a1.y, a1.z, a1.w};
            #pragma unroll
            for (int i = 0; i < 8; i++) {
                unsigned long long aa = pack2f(av[i]);
                FMA2(acc[i][0], aa, bq0.x);
                FMA2(acc[i][1], aa, bq0.y);
                FMA2(acc[i][2], aa, bq1.x);
                FMA2(acc[i][3], aa, bq1.y);
            }
        }
        if (kt < 15) STORE_AB(buf ^ 1);
        __syncthreads();
    }

    float bc[8];
    #pragma unroll
    for (int j = 0; j < 8; j++) {
        int cidx = colBase + tn + j;
        float b = (b1 != nullptr) ? b1[cidx] : 0.f;
        if (b2 != nullptr) b += b2[cidx];
        bc[j] = b;
    }
    #pragma unroll
    for (int i = 0; i < 8; i++) {
        int r = rowBase + tm + i;
        if (r < M) {
            float2 v0 = unpack2f(acc[i][0]);
            float2 v1 = unpack2f(acc[i][1]);
            float2 v2 = unpack2f(acc[i][2]);
            float2 v3 = unpack2f(acc[i][3]);
            float* cp = C + (size_t)r * Nout + colBase + tn;
            *(float4*)cp       = make_float4(v0.x + bc[0], v0.y + bc[1], v1.x + bc[2], v1.y + bc[3]);
            *(float4*)(cp + 4) = make_float4(v2.x + bc[4], v2.y + bc[5], v3.x + bc[6], v3.y + bc[7]);
        }
    }
}

// ---------------- LSTM1 first step (h=c=0) ----------------
__global__ void step0_kernel(const float* __restrict__ XW1, const int* __restrict__ edges,
                             const float* __restrict__ ew,
                             const float* __restrict__ bih1, const float* __restrict__ bhh1,
                             float* __restrict__ h, float* __restrict__ c,
                             __nv_bfloat16* __restrict__ hhi, __nv_bfloat16* __restrict__ hlo)
{
    int idx = blockIdx.x * blockDim.x + threadIdx.x;
    if (idx >= NN * 256) return;
    int n = idx >> 8, j = idx & 255;
    int e = edges[n * DD];
    float w = ew[n * DD];
    const float* x = XW1 + (size_t)e * 1024 + j;
    float ig = bih1[j]       + bhh1[j]       + w * x[0];
    float gg = bih1[512 + j] + bhh1[512 + j] + w * x[512];
    float og = bih1[768 + j] + bhh1[768 + j] + w * x[768];
    float cc = sigm(ig) * tanh_f(gg);
    float hv = sigm(og) * tanh_f(cc);
    h[idx] = hv;
    c[idx] = cc;
    __nv_bfloat16 hi, lo;
    splitbf(hv, hi, lo);
    hhi[idx] = hi;
    hlo[idx] = lo;
}

// ---------------- LSTM2: sequential over N nodes on an 8-CTA cluster ----------------
// Warp-local cell: warp w owns 4 units (rank*32 + w*4 + 0..3) x all 4 gates (16 cols).
// lane: cg = l>>4 selects gate pair {2cg, 2cg+1}; sl = l&15 is the k-chunk.
// Per-thread: 8 cols x 16 k (k-set {64j + 4sl + 0..3}), butterfly over 16 lanes,
// 2 idx-shfls deliver gates 2,3 from half 1 to cell lanes (l<4).
__global__ void __cluster_dims__(CL, 1, 1) __launch_bounds__(256, 1)
lstm2_kernel(const float* __restrict__ xw2,
             const float* __restrict__ Whh2,
             float* __restrict__ hs)
{
    __shared__ __align__(16) float h_buf[2][256];
    __shared__ __align__(8)  unsigned long long mbar[2];

    int tid = threadIdx.x;
    int w = tid >> 5, l = tid & 31;
    int cg = l >> 4, sl = l & 15;
    int rank = (int)ctarank();
    int j4 = l & 3;

    // weights: vi = gg*4 + j (gg 0..1 within this half), gate = cg*2+gg
    unsigned long long wp[8][8];
    #pragma unroll
    for (int gg = 0; gg < 2; gg++)
        #pragma unroll
        for (int j = 0; j < 4; j++) {
            int vi = gg * 4 + j;
            int gcol = (cg * 2 + gg) * 256 + rank * 32 + w * 4 + j;
            const float* wr = Whh2 + (size_t)gcol * 256;
            #pragma unroll
            for (int jj = 0; jj < 4; jj++) {
                ulonglong2 tq = *(const ulonglong2*)(wr + jj * 64 + sl * 4);
                wp[vi][2 * jj]     = tq.x;
                wp[vi][2 * jj + 1] = tq.y;
            }
        }

    uint32_t hb = smem_u32(&h_buf[0][0]);
    uint32_t mb = smem_u32(&mbar[0]);
    uint32_t rH[8], rM[8];
    #pragma unroll
    for (int d = 0; d < 8; d++) {
        asm("mapa.shared::cluster.u32 %0, %1, %2;" : "=r"(rH[d]) : "r"(hb), "r"(d));
        asm("mapa.shared::cluster.u32 %0, %1, %2;" : "=r"(rM[d]) : "r"(mb), "r"(d));
    }

    h_buf[0][tid] = 0.f;
    if (tid == 0) {
        MBAR_INIT(mb, 1);
        MBAR_INIT(mb + 8, 1);
        MBAR_ARM_TX(mb + 8, 1024);
    }
    bool cellLane = (l < 4);
    int unit = rank * 32 + w * 4 + j4;
    float c_reg = 0.f;
    float xc[4] = {0.f, 0.f, 0.f, 0.f};
    if (cellLane) {
        #pragma unroll
        for (int q = 0; q < 4; q++) xc[q] = xw2[q * 256 + unit];
    }
    __syncthreads();
    asm volatile("barrier.cluster.arrive.aligned;" ::: "memory");
    asm volatile("barrier.cluster.wait.aligned;" ::: "memory");

    int p = 0;
    for (int n = 0; n < NN; n++) {
        float xnx[4] = {0.f, 0.f, 0.f, 0.f};
        if (cellLane && n + 1 < NN) {
            const float* xp = xw2 + (size_t)(n + 1) * 1024 + unit;
            #pragma unroll
            for (int q = 0; q < 4; q++) xnx[q] = xp[q * 256];
        }

        const float* hp = &h_buf[p][0];
        unsigned long long acc[8];
        #pragma unroll
        for (int c = 0; c < 8; c++) acc[c] = 0ull;
        #pragma unroll
        for (int jj = 0; jj < 4; jj++) {
            ulonglong2 hv = *(const ulonglong2*)(hp + jj * 64 + sl * 4);
            #pragma unroll
            for (int c = 0; c < 8; c++) {
                FMA2(acc[c], hv.x, wp[c][2 * jj]);
                FMA2(acc[c], hv.y, wp[c][2 * jj + 1]);
            }
        }
        float v[8];
        #pragma unroll
        for (int c = 0; c < 8; c++) { float2 tv = unpack2f(acc[c]); v[c] = tv.x + tv.y; }
        #pragma unroll
        for (int m = 1; m < 16; m <<= 1)
            #pragma unroll
            for (int c = 0; c < 8; c++)
                v[c] += __shfl_xor_sync(0xffffffffu, v[c], m);

        // half 1 lanes select their own unit's gate-2/3 values; cell lanes fetch by idx
        float tg = v[j4], to = v[4 + j4];
        float gv = __shfl_sync(0xffffffffu, tg, j4 + 16);
        float ov = __shfl_sync(0xffffffffu, to, j4 + 16);

        if (tid == 0) MBAR_ARM_TX(mb + (uint32_t)p * 8, 1024);
        __syncthreads();

        if (cellLane) {
            float ig = v[j4]     + xc[0];
            float fg = v[4 + j4] + xc[1];
            float gg = gv        + xc[2];
            float og = ov        + xc[3];
            c_reg = sigm(fg) * c_reg + sigm(ig) * tanh_f(gg);
            float hn = sigm(og) * tanh_f(c_reg);
            if (n + 1 < NN) {
                uint32_t voff  = (uint32_t)((p ^ 1) * 256 + unit) * 4u;
                uint32_t mboff = (uint32_t)(p ^ 1) * 8u;
                uint32_t bits  = __float_as_uint(hn);
                #pragma unroll
                for (int d = 0; d < 8; d++)
                    ST_ASYNC_F32(rH[d] + voff, bits, rM[d] + mboff);
            }
            hs[(size_t)n * 256 + unit] = hn;
            xc[0] = xnx[0]; xc[1] = xnx[1]; xc[2] = xnx[2]; xc[3] = xnx[3];
        }

        if (n + 1 < NN) {
            uint32_t ph = (uint32_t)((n >> 1) & 1);
            MBAR_WAIT_CLUSTER(mb + (uint32_t)(p ^ 1) * 8, ph);
        }
        p ^= 1;
    }
}

// ---------------- launch ----------------
extern "C" void kernel_launch(void* const* d_in, const int* in_sizes, int n_in,
                              void* d_out, int out_size)
{
    const float* node_feats = (const float*)d_in[0];
    const int*   edges      = (const int*)d_in[1];
    const float* ew         = (const float*)d_in[2];
    const float* Wih1       = (const float*)d_in[3];
    const float* Whh1       = (const float*)d_in[4];
    const float* bih1       = (const float*)d_in[5];
    const float* bhh1       = (const float*)d_in[6];
    const float* Wih2       = (const float*)d_in[7];
    const float* Whh2       = (const float*)d_in[8];
    const float* bih2       = (const float*)d_in[9];
    const float* bhh2       = (const float*)d_in[10];
    const float* Wl         = (const float*)d_in[11];
    const float* bl         = (const float*)d_in[12];
    const float* bias       = (const float*)d_in[13];
    float* out = (float*)d_out;

    void *pXW1, *pGates, *pH1, *pHB, *pC1, *pHs, *pHA, *pLA, *pHBs, *pLB;
    cudaGetSymbolAddress(&pXW1,   g_XW1);
    cudaGetSymbolAddress(&pGates, g_gates);
    cudaGetSymbolAddress(&pH1,    g_h1);
    cudaGetSymbolAddress(&pHB,    g_hB);
    cudaGetSymbolAddress(&pC1,    g_c1);
    cudaGetSymbolAddress(&pHs,    g_hs);
    cudaGetSymbolAddress(&pHA,    g_hhA);
    cudaGetSymbolAddress(&pLA,    g_hlA);
    cudaGetSymbolAddress(&pHBs,   g_hhB);
    cudaGetSymbolAddress(&pLB,    g_hlB);
    float* XW1   = (float*)pXW1;
    float* gates = (float*)pGates;
    float* h1    = (float*)pH1;
    float* hB    = (float*)pHB;
    float* c1    = (float*)pC1;
    float* hs    = (float*)pHs;
    __nv_bfloat16* hhA = (__nv_bfloat16*)pHA;
    __nv_bfloat16* hlA = (__nv_bfloat16*)pLA;
    __nv_bfloat16* hhB = (__nv_bfloat16*)pHBs;
    __nv_bfloat16* hlB = (__nv_bfloat16*)pLB;

    cudaFuncSetAttribute(fused_hmma_step,
                         cudaFuncAttributeMaxDynamicSharedMemorySize, SMEM_FUSED);

    dim3 blk(256);
    dim3 grid_g(8, 79);
    int ew_blocks = (NN * 256 + 255) / 256;

    // XW1 = node_feats @ Wih1^T
    gemm256_kernel<<<grid_g, blk>>>(node_feats, Wih1, XW1, NN, 1024, nullptr, nullptr);
    // split Whh1 -> bf16 hi/lo, bias sums
    split_w_kernel<<<1024, 256>>>(Whh1, bih1, bhh1);
    // t = 0
    step0_kernel<<<ew_blocks, blk>>>(XW1, edges, ew, bih1, bhh1, h1, c1, hhA, hlA);
    // t = 1..31: fused HMMA step v3
    float* hinF = h1;   float* houtF = hB;
    __nv_bfloat16 *hinH = hhA, *hinL = hlA, *houtH = hhB, *houtL = hlB;
    dim3 grid_f(8, 157);
    for (int t = 1; t < DD; t++) {
        fused_hmma_step<<<grid_f, blk, SMEM_FUSED>>>(hinH, hinL, XW1, edges, ew, t,
                                                     houtF, houtH, houtL, c1);
        float* tf = hinF; hinF = houtF; houtF = tf;
        __nv_bfloat16* th = hinH; hinH = houtH; houtH = th;
        __nv_bfloat16* tl = hinL; hinL = houtL; houtL = tl;
    }
    // XW2 = h_agg @ Wih2^T + (bih2+bhh2)
    gemm256_kernel<<<grid_g, blk>>>(hinF, Wih2, gates, NN, 1024, bih2, bhh2);
    // sequential LSTM2 on an 8-CTA cluster
    lstm2_kernel<<<CL, blk>>>(gates, Whh2, hs);
    // out = hs @ Wl^T + bl + bias
    dim3 grid_fin(2, 79);
    gemm256_kernel<<<grid_fin, blk>>>(hs, Wl, out, NN, 256, bl, bias);
    (void)in_sizes; (void)n_in; (void)out_size;
}

// round 15
// speedup vs baseline: 1.0084x; 1.0084x over previous
#include <cuda_runtime.h>
#include <cuda_bf16.h>
#include <cstdint>

#define NN 10000
#define DD 32
#define CL 8

// ---------------- device scratch (no allocation allowed) ----------------
__device__ float g_XW1[NN * 1024];    // node_feats @ Wih1^T
__device__ float g_gates[NN * 1024];  // XW2 scratch
__device__ float g_h1[NN * 256];
__device__ float g_hB[NN * 256];
__device__ float g_c1[NN * 256];
__device__ float g_hs[NN * 256];
__device__ __nv_bfloat16 g_W1h[1024 * 256];
__device__ __nv_bfloat16 g_W1l[1024 * 256];
__device__ float g_bsum[1024];
__device__ __nv_bfloat16 g_hhA[NN * 256];
__device__ __nv_bfloat16 g_hlA[NN * 256];
__device__ __nv_bfloat16 g_hhB[NN * 256];
__device__ __nv_bfloat16 g_hlB[NN * 256];

// ---------------- helpers ----------------
__device__ __forceinline__ unsigned long long pack2f(float x) {
    unsigned long long r;
    asm("mov.b64 %0, {%1, %1};" : "=l"(r) : "f"(x));
    return r;
}
__device__ __forceinline__ float2 unpack2f(unsigned long long v) {
    float2 r;
    asm("mov.b64 {%0, %1}, %2;" : "=f"(r.x), "=f"(r.y) : "l"(v));
    return r;
}
#define FMA2(acc, a, b) asm("fma.rn.f32x2 %0, %1, %2, %0;" : "+l"(acc) : "l"(a), "l"(b))

__device__ __forceinline__ float sigm(float x)   { return 1.f / (1.f + __expf(-x)); }
__device__ __forceinline__ float tanh_f(float x) { return 1.f - 2.f / (__expf(2.f * x) + 1.f); }

__device__ __forceinline__ uint32_t smem_u32(const void* p) {
    uint32_t a;
    asm("{ .reg .u64 t; cvta.to.shared.u64 t, %1; cvt.u32.u64 %0, t; }" : "=r"(a) : "l"(p));
    return a;
}
__device__ __forceinline__ uint32_t ctarank() {
    uint32_t r; asm("mov.u32 %0, %%cluster_ctarank;" : "=r"(r)); return r;
}

#define MBAR_INIT(addr, cnt) \
    asm volatile("mbarrier.init.shared.b64 [%0], %1;" :: "r"((uint32_t)(addr)), "r"((uint32_t)(cnt)) : "memory")

#define MBAR_ARM_TX(addr, tx) \
    asm volatile("mbarrier.arrive.expect_tx.shared.b64 _, [%0], %1;" :: "r"((uint32_t)(addr)), "r"((uint32_t)(tx)) : "memory")

#define MBAR_WAIT_CLUSTER(addr, ph) do {                                              \
    uint32_t _done = 0;                                                               \
    while (!_done) {                                                                  \
        asm volatile("{\n\t.reg .pred p;\n\t"                                         \
            "mbarrier.try_wait.parity.acquire.cluster.shared::cta.b64 p, [%1], %2;\n\t" \
            "selp.b32 %0, 1, 0, p;\n\t}"                                              \
            : "=r"(_done) : "r"((uint32_t)(addr)), "r"((uint32_t)(ph)) : "memory");   \
    }                                                                                 \
} while (0)

#define ST_ASYNC_F32(raddr, bits, rmbar) \
    asm volatile("st.async.weak.shared::cluster.mbarrier::complete_tx::bytes.b32 [%0], %1, [%2];" \
                 :: "r"(raddr), "r"(bits), "r"(rmbar) : "memory")

__device__ __forceinline__ void splitbf(float v, __nv_bfloat16& hi, __nv_bfloat16& lo) {
    hi = __float2bfloat16(v);
    lo = __float2bfloat16(v - __bfloat162float(hi));
}

// ---- mma.sync / ldmatrix / cp.async (portable sm_80+ path) ----
__device__ __forceinline__ void ldm_x4(uint32_t* r, uint32_t addr) {
    asm volatile("ldmatrix.sync.aligned.m8n8.x4.shared.b16 {%0,%1,%2,%3}, [%4];"
        : "=r"(r[0]), "=r"(r[1]), "=r"(r[2]), "=r"(r[3]) : "r"(addr));
}
__device__ __forceinline__ void ldm_x2(uint32_t* r, uint32_t addr) {
    asm volatile("ldmatrix.sync.aligned.m8n8.x2.shared.b16 {%0,%1}, [%2];"
        : "=r"(r[0]), "=r"(r[1]) : "r"(addr));
}
__device__ __forceinline__ void mma16816(float* d, const uint32_t* a, const uint32_t* b) {
    asm volatile(
        "mma.sync.aligned.m16n8k16.row.col.f32.bf16.bf16.f32 "
        "{%0,%1,%2,%3}, {%4,%5,%6,%7}, {%8,%9}, {%0,%1,%2,%3};"
        : "+f"(d[0]), "+f"(d[1]), "+f"(d[2]), "+f"(d[3])
        : "r"(a[0]), "r"(a[1]), "r"(a[2]), "r"(a[3]), "r"(b[0]), "r"(b[1]));
}
#define CP_ASYNC16(dst, src) \
    asm volatile("cp.async.cg.shared.global [%0], [%1], 16;" :: "r"(dst), "l"(src) : "memory")
#define CP_COMMIT() asm volatile("cp.async.commit_group;" ::: "memory")
#define CP_WAIT(n)  asm volatile("cp.async.wait_group %0;" :: "n"(n) : "memory")

// ================= FUSED HMMA step v3: 3-stage pipeline, 1 sync/kt =================
#define STG_BYTES 18432
#define SMEM_FUSED (3 * STG_BYTES)
__global__ __launch_bounds__(256, 3) void fused_hmma_step(
    const __nv_bfloat16* __restrict__ hh, const __nv_bfloat16* __restrict__ hl,
    const float* __restrict__ XW1, const int* __restrict__ edges,
    const float* __restrict__ ew, int t,
    float* __restrict__ houtF, __nv_bfloat16* __restrict__ houth,
    __nv_bfloat16* __restrict__ houtl, float* __restrict__ cbuf)
{
    extern __shared__ __align__(16) char dsm[];
    uint32_t sb = smem_u32(dsm);

    int tid = threadIdx.x, wid = tid >> 5, lane = tid & 31;
    int wm = wid >> 2, nw = wid & 3;
    int u0 = blockIdx.x * 32;
    int rowBase = blockIdx.y * 64;

    int q4 = lane >> 3;
    uint32_t aOff = (uint32_t)((wm * 32 + (q4 & 1) * 8 + (lane & 7)) * 48 + (q4 >> 1) * 16);
    int ql = lane & 15, q2 = ql >> 3;
    uint32_t bOff = (uint32_t)((nw * 8 + (ql & 7)) * 48 + q2 * 16);

    uint32_t aBase[3][2], bBase[3][2];
    #pragma unroll
    for (int b = 0; b < 3; b++)
        #pragma unroll
        for (int s = 0; s < 2; s++) {
            aBase[b][s] = sb + (uint32_t)(b * STG_BYTES + s * 3072) + aOff;
            bBase[b][s] = sb + (uint32_t)(b * STG_BYTES + 6144 + s * 6144) + bOff;
        }

    float acc[2][4][4];
    #pragma unroll
    for (int mt = 0; mt < 2; mt++)
        #pragma unroll
        for (int g = 0; g < 4; g++)
            #pragma unroll
            for (int e = 0; e < 4; e++) acc[mt][g][e] = 0.f;

#define H2_ISSUE(kt_, b_) do { \
    int k0_ = (kt_) * 16; \
    uint32_t stg_ = sb + (uint32_t)((b_) * STG_BYTES); \
    _Pragma("unroll") \
    for (int rep_ = 0; rep_ < 3; rep_++) { \
        int c_ = rep_ * 256 + tid; \
        int slot_ = c_ >> 1, half_ = c_ & 1; \
        uint32_t dst_; const __nv_bfloat16* src_; \
        if (slot_ < 128) { \
            int sel_ = slot_ >> 6, row_ = slot_ & 63; \
            int gr_ = rowBase + row_; if (gr_ >= NN) gr_ = NN - 1; \
            src_ = (sel_ ? hl : hh) + (size_t)gr_ * 256 + k0_ + half_ * 8; \
            dst_ = stg_ + (uint32_t)(sel_ * 3072 + row_ * 48 + half_ * 16); \
        } else { \
            int s2_ = slot_ - 128; \
            int sel_ = s2_ >> 7, j_ = s2_ & 127; \
            int wrow_ = (j_ >> 5) * 256 + u0 + (j_ & 31); \
            src_ = (sel_ ? g_W1l : g_W1h) + (size_t)wrow_ * 256 + k0_ + half_ * 8; \
            dst_ = stg_ + (uint32_t)(6144 + sel_ * 6144 + j_ * 48 + half_ * 16); \
        } \
        CP_ASYNC16(dst_, src_); \
    } \
    CP_COMMIT(); \
} while (0)

    H2_ISSUE(0, 0);
    H2_ISSUE(1, 1);

    #pragma unroll 1
    for (int kt = 0; kt < 16; kt++) {
        int buf = kt % 3;
        __syncthreads();
        if (kt + 2 < 16) { H2_ISSUE(kt + 2, (kt + 2) % 3); CP_WAIT(2); }
        else if (kt + 1 < 16) { CP_WAIT(1); }
        else { CP_WAIT(0); }

        uint32_t ahh[2][4], ahl[2][4], bwh[4][2], bwl[4][2];
        #pragma unroll
        for (int mt = 0; mt < 2; mt++) {
            ldm_x4(ahh[mt], aBase[buf][0] + (uint32_t)(mt * 768));
            ldm_x4(ahl[mt], aBase[buf][1] + (uint32_t)(mt * 768));
        }
        #pragma unroll
        for (int g = 0; g < 4; g++) {
            ldm_x2(bwh[g], bBase[buf][0] + (uint32_t)(g * 1536));
            ldm_x2(bwl[g], bBase[buf][1] + (uint32_t)(g * 1536));
        }
        #pragma unroll
        for (int mt = 0; mt < 2; mt++)
            #pragma unroll
            for (int g = 0; g < 4; g++) {
                mma16816(acc[mt][g], ahh[mt], bwh[g]);
                mma16816(acc[mt][g], ahh[mt], bwl[g]);
                mma16816(acc[mt][g], ahl[mt], bwh[g]);
            }
    }

    // ---- epilogue: bias + gather + cell ----
    int uc = u0 + nw * 8 + (lane & 3) * 2;
    #pragma unroll
    for (int mt = 0; mt < 2; mt++) {
        #pragma unroll
        for (int half = 0; half < 2; half++) {
            int r = rowBase + wm * 32 + mt * 16 + (lane >> 2) + half * 8;
            if (r < NN) {
                int eI = edges[r * DD + t];
                float wgt = ew[r * DD + t];
                const float* xr = XW1 + (size_t)eI * 1024;
                float2 xi = *(const float2*)(xr + uc);
                float2 xf = *(const float2*)(xr + 256 + uc);
                float2 xg = *(const float2*)(xr + 512 + uc);
                float2 xo = *(const float2*)(xr + 768 + uc);
                float* cp = cbuf + (size_t)r * 256 + uc;
                float2 cc = *(float2*)cp;
                float hn[2];
                #pragma unroll
                for (int s = 0; s < 2; s++) {
                    int e = half * 2 + s;
                    float vi = acc[mt][0][e] + g_bsum[uc + s]       + wgt * (s ? xi.y : xi.x);
                    float vf = acc[mt][1][e] + g_bsum[256 + uc + s] + wgt * (s ? xf.y : xf.x);
                    float vg = acc[mt][2][e] + g_bsum[512 + uc + s] + wgt * (s ? xg.y : xg.x);
                    float vo = acc[mt][3][e] + g_bsum[768 + uc + s] + wgt * (s ? xo.y : xo.x);
                    float c2 = sigm(vf) * (s ? cc.y : cc.x) + sigm(vi) * tanh_f(vg);
                    if (s) cc.y = c2; else cc.x = c2;
                    hn[s] = sigm(vo) * tanh_f(c2);
                }
                *(float2*)cp = cc;
                *(float2*)(houtF + (size_t)r * 256 + uc) = make_float2(hn[0], hn[1]);
                __nv_bfloat16 a, al, b, bl;
                splitbf(hn[0], a, al);
                splitbf(hn[1], b, bl);
                *(__nv_bfloat162*)(houth + (size_t)r * 256 + uc) = __halves2bfloat162(a, b);
                *(__nv_bfloat162*)(houtl + (size_t)r * 256 + uc) = __halves2bfloat162(al, bl);
            }
        }
    }
}

// ---------------- one-time: split Whh1 into bf16 hi/lo + bias sum ----------------
__global__ void split_w_kernel(const float* __restrict__ Whh1,
                               const float* __restrict__ bih1, const float* __restrict__ bhh1)
{
    int idx = blockIdx.x * 256 + threadIdx.x;
    if (idx < 1024 * 256) {
        __nv_bfloat16 hi, lo;
        splitbf(Whh1[idx], hi, lo);
        g_W1h[idx] = hi;
        g_W1l[idx] = lo;
    }
    if (idx < 1024) g_bsum[idx] = bih1[idx] + bhh1[idx];
}

// ---------------- generic K=256 fp32 GEMM: C = A @ W^T (+b1+b2) ----------------
#define LOAD_AB(off) do { \
    if (aval) { ra0 = *(const float4*)(Arow + (off)); ra1 = *(const float4*)(Arow + (off) + 4); } \
    else      { ra0 = zf4; ra1 = zf4; } \
    rb0 = *(const float4*)(Wrow + (off)); rb1 = *(const float4*)(Wrow + (off) + 4); \
} while (0)

#define STORE_AB(buf) do { \
    As[buf][lc+0][lr]=ra0.x; As[buf][lc+1][lr]=ra0.y; As[buf][lc+2][lr]=ra0.z; As[buf][lc+3][lr]=ra0.w; \
    As[buf][lc+4][lr]=ra1.x; As[buf][lc+5][lr]=ra1.y; As[buf][lc+6][lr]=ra1.z; As[buf][lc+7][lr]=ra1.w; \
    Bs[buf][lc+0][lr]=rb0.x; Bs[buf][lc+1][lr]=rb0.y; Bs[buf][lc+2][lr]=rb0.z; Bs[buf][lc+3][lr]=rb0.w; \
    Bs[buf][lc+4][lr]=rb1.x; Bs[buf][lc+5][lr]=rb1.y; Bs[buf][lc+6][lr]=rb1.z; Bs[buf][lc+7][lr]=rb1.w; \
} while (0)

__global__ __launch_bounds__(256, 2) void gemm256_kernel(
    const float* __restrict__ A, const float* __restrict__ W,
    float* __restrict__ C, int M, int Nout,
    const float* __restrict__ b1, const float* __restrict__ b2)
{
    __shared__ __align__(16) float As[2][16][128];
    __shared__ __align__(16) float Bs[2][16][128];

    int tid = threadIdx.x;
    int rowBase = blockIdx.y * 128;
    int colBase = blockIdx.x * 128;

    int lr = tid >> 1;
    int lc = (tid & 1) * 8;
    int ar = rowBase + lr;
    const float* Arow = A + (size_t)ar * 256 + lc;
    const float* Wrow = W + (size_t)(colBase + lr) * 256 + lc;
    bool aval = (ar < M);
    float4 zf4 = make_float4(0.f, 0.f, 0.f, 0.f);

    int tm = (tid >> 4) * 8;
    int tn = (tid & 15) * 8;

    unsigned long long acc[8][4];
    #pragma unroll
    for (int i = 0; i < 8; i++)
        #pragma unroll
        for (int j = 0; j < 4; j++) acc[i][j] = 0ull;

    float4 ra0, ra1, rb0, rb1;
    LOAD_AB(0);
    STORE_AB(0);
    __syncthreads();

    #pragma unroll 1
    for (int kt = 0; kt < 16; kt++) {
        int buf = kt & 1;
        if (kt < 15) LOAD_AB((kt + 1) * 16);
        #pragma unroll
        for (int kk = 0; kk < 16; kk++) {
            float4 a0 = *(const float4*)&As[buf][kk][tm];
            float4 a1 = *(const float4*)&As[buf][kk][tm + 4];
            ulonglong2 bq0 = *(const ulonglong2*)&Bs[buf][kk][tn];
            ulonglong2 bq1 = *(const ulonglong2*)&Bs[buf][kk][tn + 4];
            float av[8] = {a0.x, a0.y, a0.z, a0.w, a1.x, a1.y, a1.z, a1.w};
            #pragma unroll
            for (int i = 0; i < 8; i++) {
                unsigned long long aa = pack2f(av[i]);
                FMA2(acc[i][0], aa, bq0.x);
                FMA2(acc[i][1], aa, bq0.y);
                FMA2(acc[i][2], aa, bq1.x);
                FMA2(acc[i][3], aa, bq1.y);
            }
        }
        if (kt < 15) STORE_AB(buf ^ 1);
        __syncthreads();
    }

    float bc[8];
    #pragma unroll
    for (int j = 0; j < 8; j++) {
        int cidx = colBase + tn + j;
        float b = (b1 != nullptr) ? b1[cidx] : 0.f;
        if (b2 != nullptr) b += b2[cidx];
        bc[j] = b;
    }
    #pragma unroll
    for (int i = 0; i < 8; i++) {
        int r = rowBase + tm + i;
        if (r < M) {
            float2 v0 = unpack2f(acc[i][0]);
            float2 v1 = unpack2f(acc[i][1]);
            float2 v2 = unpack2f(acc[i][2]);
            float2 v3 = unpack2f(acc[i][3]);
            float* cp = C + (size_t)r * Nout + colBase + tn;
            *(float4*)cp       = make_float4(v0.x + bc[0], v0.y + bc[1], v1.x + bc[2], v1.y + bc[3]);
            *(float4*)(cp + 4) = make_float4(v2.x + bc[4], v2.y + bc[5], v3.x + bc[6], v3.y + bc[7]);
        }
    }
}

// ---------------- LSTM1 first step (h=c=0) ----------------
__global__ void step0_kernel(const float* __restrict__ XW1, const int* __restrict__ edges,
                             const float* __restrict__ ew,
                             const float* __restrict__ bih1, const float* __restrict__ bhh1,
                             float* __restrict__ h, float* __restrict__ c,
                             __nv_bfloat16* __restrict__ hhi, __nv_bfloat16* __restrict__ hlo)
{
    int idx = blockIdx.x * blockDim.x + threadIdx.x;
    if (idx >= NN * 256) return;
    int n = idx >> 8, j = idx & 255;
    int e = edges[n * DD];
    float w = ew[n * DD];
    const float* x = XW1 + (size_t)e * 1024 + j;
    float ig = bih1[j]       + bhh1[j]       + w * x[0];
    float gg = bih1[512 + j] + bhh1[512 + j] + w * x[512];
    float og = bih1[768 + j] + bhh1[768 + j] + w * x[768];
    float cc = sigm(ig) * tanh_f(gg);
    float hv = sigm(og) * tanh_f(cc);
    h[idx] = hv;
    c[idx] = cc;
    __nv_bfloat16 hi, lo;
    splitbf(hv, hi, lo);
    hhi[idx] = hi;
    hlo[idx] = lo;
}

// ---------------- LSTM2: R9 structure + dual-warp cell/broadcast split ----------------
// Warps 0 and 1 replicate the identical cell update (deterministic); warp 0 sends
// st.async to destinations 0-3 and writes hs, warp 1 sends to destinations 4-7.
__global__ void __cluster_dims__(CL, 1, 1) __launch_bounds__(256, 1)
lstm2_kernel(const float* __restrict__ xw2,
             const float* __restrict__ Whh2,
             float* __restrict__ hs)
{
    __shared__ __align__(16) float h_buf[2][256];
    __shared__ __align__(16) float sg[128];
    __shared__ __align__(8)  unsigned long long mbar[2];

    int tid = threadIdx.x;
    int w = tid >> 5, l = tid & 31;
    int half = l >> 4, sl = l & 15;
    int rank = (int)ctarank();
    int lc0 = w * 16 + half * 8;

    unsigned long long wp[8][8];
    #pragma unroll
    for (int c = 0; c < 8; c++) {
        int lc = lc0 + c;
        int gcol = (lc >> 5) * 256 + rank * 32 + (lc & 31);
        const float* wr = Whh2 + (size_t)gcol * 256;
        #pragma unroll
        for (int j = 0; j < 4; j++) {
            ulonglong2 tq = *(const ulonglong2*)(wr + j * 64 + sl * 4);
            wp[c][2 * j]     = tq.x;
            wp[c][2 * j + 1] = tq.y;
        }
    }

    uint32_t hb = smem_u32(&h_buf[0][0]);
    uint32_t mb = smem_u32(&mbar[0]);
    uint32_t rH[8], rM[8];
    #pragma unroll
    for (int d = 0; d < 8; d++) {
        asm("mapa.shared::cluster.u32 %0, %1, %2;" : "=r"(rH[d]) : "r"(hb), "r"(d));
        asm("mapa.shared::cluster.u32 %0, %1, %2;" : "=r"(rM[d]) : "r"(mb), "r"(d));
    }

    h_buf[0][tid] = 0.f;
    if (tid == 0) {
        MBAR_INIT(mb, 1);
        MBAR_INIT(mb + 8, 1);
        MBAR_ARM_TX(mb + 8, 1024);
    }
    bool cellT = (tid < 64);   // warps 0 and 1
    int cw = tid >> 5;         // which cell warp (0/1)
    int ul = tid & 31;         // unit lane
    float c_reg = 0.f;
    float xc[4] = {0.f, 0.f, 0.f, 0.f};
    if (cellT) {
        #pragma unroll
        for (int q = 0; q < 4; q++) xc[q] = xw2[q * 256 + rank * 32 + ul];
    }
    __syncthreads();
    asm volatile("barrier.cluster.arrive.aligned;" ::: "memory");
    asm volatile("barrier.cluster.wait.aligned;" ::: "memory");

    int p = 0;
    for (int n = 0; n < NN; n++) {
        float xnx[4] = {0.f, 0.f, 0.f, 0.f};
        if (cellT && n + 1 < NN) {
            const float* xp = xw2 + (size_t)(n + 1) * 1024 + rank * 32 + ul;
            #pragma unroll
            for (int q = 0; q < 4; q++) xnx[q] = xp[q * 256];
        }

        const float* hp = &h_buf[p][0];
        unsigned long long acc[8];
        #pragma unroll
        for (int c = 0; c < 8; c++) acc[c] = 0ull;
        #pragma unroll
        for (int j = 0; j < 4; j++) {
            ulonglong2 hv = *(const ulonglong2*)(hp + j * 64 + sl * 4);
            #pragma unroll
            for (int c = 0; c < 8; c++) {
                FMA2(acc[c], hv.x, wp[c][2 * j]);
                FMA2(acc[c], hv.y, wp[c][2 * j + 1]);
            }
        }
        float v[8];
        #pragma unroll
        for (int c = 0; c < 8; c++) { float2 tv = unpack2f(acc[c]); v[c] = tv.x + tv.y; }
        #pragma unroll
        for (int m = 1; m < 16; m <<= 1)
            #pragma unroll
            for (int c = 0; c < 8; c++)
                v[c] += __shfl_xor_sync(0xffffffffu, v[c], m);
        if (sl == 0) {
            *(float4*)&sg[lc0]     = make_float4(v[0], v[1], v[2], v[3]);
            *(float4*)&sg[lc0 + 4] = make_float4(v[4], v[5], v[6], v[7]);
        }
        if (tid == 0) MBAR_ARM_TX(mb + (uint32_t)p * 8, 1024);
        __syncthreads();

        if (cellT) {
            float ig = sg[ul]       + xc[0];
            float fg = sg[32 + ul]  + xc[1];
            float gg = sg[64 + ul]  + xc[2];
            float og = sg[96 + ul]  + xc[3];
            c_reg = sigm(fg) * c_reg + sigm(ig) * tanh_f(gg);
            float hn = sigm(og) * tanh_f(c_reg);
            if (n + 1 < NN) {
                uint32_t voff  = (uint32_t)((p ^ 1) * 256 + rank * 32 + ul) * 4u;
                uint32_t mboff = (uint32_t)(p ^ 1) * 8u;
                uint32_t bits  = __float_as_uint(hn);
                #pragma unroll
                for (int d2 = 0; d2 < 4; d2++) {
                    int d = cw * 4 + d2;
                    ST_ASYNC_F32(rH[d] + voff, bits, rM[d] + mboff);
                }
            }
            if (cw == 0) hs[(size_t)n * 256 + rank * 32 + ul] = hn;
            xc[0] = xnx[0]; xc[1] = xnx[1]; xc[2] = xnx[2]; xc[3] = xnx[3];
        }

        if (n + 1 < NN) {
            uint32_t ph = (uint32_t)((n >> 1) & 1);
            MBAR_WAIT_CLUSTER(mb + (uint32_t)(p ^ 1) * 8, ph);
        }
        p ^= 1;
    }
}

// ---------------- launch ----------------
extern "C" void kernel_launch(void* const* d_in, const int* in_sizes, int n_in,
                              void* d_out, int out_size)
{
    const float* node_feats = (const float*)d_in[0];
    const int*   edges      = (const int*)d_in[1];
    const float* ew         = (const float*)d_in[2];
    const float* Wih1       = (const float*)d_in[3];
    const float* Whh1       = (const float*)d_in[4];
    const float* bih1       = (const float*)d_in[5];
    const float* bhh1       = (const float*)d_in[6];
    const float* Wih2       = (const float*)d_in[7];
    const float* Whh2       = (const float*)d_in[8];
    const float* bih2       = (const float*)d_in[9];
    const float* bhh2       = (const float*)d_in[10];
    const float* Wl         = (const float*)d_in[11];
    const float* bl         = (const float*)d_in[12];
    const float* bias       = (const float*)d_in[13];
    float* out = (float*)d_out;

    void *pXW1, *pGates, *pH1, *pHB, *pC1, *pHs, *pHA, *pLA, *pHBs, *pLB;
    cudaGetSymbolAddress(&pXW1,   g_XW1);
    cudaGetSymbolAddress(&pGates, g_gates);
    cudaGetSymbolAddress(&pH1,    g_h1);
    cudaGetSymbolAddress(&pHB,    g_hB);
    cudaGetSymbolAddress(&pC1,    g_c1);
    cudaGetSymbolAddress(&pHs,    g_hs);
    cudaGetSymbolAddress(&pHA,    g_hhA);
    cudaGetSymbolAddress(&pLA,    g_hlA);
    cudaGetSymbolAddress(&pHBs,   g_hhB);
    cudaGetSymbolAddress(&pLB,    g_hlB);
    float* XW1   = (float*)pXW1;
    float* gates = (float*)pGates;
    float* h1    = (float*)pH1;
    float* hB    = (float*)pHB;
    float* c1    = (float*)pC1;
    float* hs    = (float*)pHs;
    __nv_bfloat16* hhA = (__nv_bfloat16*)pHA;
    __nv_bfloat16* hlA = (__nv_bfloat16*)pLA;
    __nv_bfloat16* hhB = (__nv_bfloat16*)pHBs;
    __nv_bfloat16* hlB = (__nv_bfloat16*)pLB;

    cudaFuncSetAttribute(fused_hmma_step,
                         cudaFuncAttributeMaxDynamicSharedMemorySize, SMEM_FUSED);

    dim3 blk(256);
    dim3 grid_g(8, 79);
    int ew_blocks = (NN * 256 + 255) / 256;

    // XW1 = node_feats @ Wih1^T
    gemm256_kernel<<<grid_g, blk>>>(node_feats, Wih1, XW1, NN, 1024, nullptr, nullptr);
    // split Whh1 -> bf16 hi/lo, bias sums
    split_w_kernel<<<1024, 256>>>(Whh1, bih1, bhh1);
    // t = 0
    step0_kernel<<<ew_blocks, blk>>>(XW1, edges, ew, bih1, bhh1, h1, c1, hhA, hlA);
    // t = 1..31: fused HMMA step v3
    float* hinF = h1;   float* houtF = hB;
    __nv_bfloat16 *hinH = hhA, *hinL = hlA, *houtH = hhB, *houtL = hlB;
    dim3 grid_f(8, 157);
    for (int t = 1; t < DD; t++) {
        fused_hmma_step<<<grid_f, blk, SMEM_FUSED>>>(hinH, hinL, XW1, edges, ew, t,
                                                     houtF, houtH, houtL, c1);
        float* tf = hinF; hinF = houtF; houtF = tf;
        __nv_bfloat16* th = hinH; hinH = houtH; houtH = th;
        __nv_bfloat16* tl = hinL; hinL = houtL; houtL = tl;
    }
    // XW2 = h_agg @ Wih2^T + (bih2+bhh2)
    gemm256_kernel<<<grid_g, blk>>>(hinF, Wih2, gates, NN, 1024, bih2, bhh2);
    // sequential LSTM2 on an 8-CTA cluster
    lstm2_kernel<<<CL, blk>>>(gates, Whh2, hs);
    // out = hs @ Wl^T + bl + bias
    dim3 grid_fin(2, 79);
    gemm256_kernel<<<grid_fin, blk>>>(hs, Wl, out, NN, 256, bl, bias);
    (void)in_sizes; (void)n_in; (void)out_size;
}

// round 17
// speedup vs baseline: 1.0594x; 1.0506x over previous
#include <cuda_runtime.h>
#include <cuda_bf16.h>
#include <cstdint>

#define NN 10000
#define DD 32
#define CL 8

// ---------------- device scratch (no allocation allowed) ----------------
__device__ float g_XW1[NN * 1024];    // node_feats @ Wih1^T
__device__ float g_gates[NN * 1024];  // XW2 scratch
__device__ float g_h1[NN * 256];
__device__ float g_hB[NN * 256];
__device__ float g_c1[NN * 256];
__device__ float g_hs[NN * 256];
__device__ __nv_bfloat16 g_W1h[1024 * 256];   // Whh1 split
__device__ __nv_bfloat16 g_W1l[1024 * 256];
__device__ __nv_bfloat16 g_W2h[1024 * 256];   // Wih2 split
__device__ __nv_bfloat16 g_W2l[1024 * 256];
__device__ __nv_bfloat16 g_Wi1h[1024 * 256];  // Wih1 split
__device__ __nv_bfloat16 g_Wi1l[1024 * 256];
__device__ float g_bsum[1024];    // bih1+bhh1
__device__ float g_bsum2[1024];   // bih2+bhh2
__device__ __nv_bfloat16 g_nfh[NN * 256];     // node_feats split
__device__ __nv_bfloat16 g_nfl[NN * 256];
__device__ __nv_bfloat16 g_hhA[NN * 256];
__device__ __nv_bfloat16 g_hlA[NN * 256];
__device__ __nv_bfloat16 g_hhB[NN * 256];
__device__ __nv_bfloat16 g_hlB[NN * 256];

// ---------------- helpers ----------------
__device__ __forceinline__ unsigned long long pack2f(float x) {
    unsigned long long r;
    asm("mov.b64 %0, {%1, %1};" : "=l"(r) : "f"(x));
    return r;
}
__device__ __forceinline__ float2 unpack2f(unsigned long long v) {
    float2 r;
    asm("mov.b64 {%0, %1}, %2;" : "=f"(r.x), "=f"(r.y) : "l"(v));
    return r;
}
#define FMA2(acc, a, b) asm("fma.rn.f32x2 %0, %1, %2, %0;" : "+l"(acc) : "l"(a), "l"(b))

__device__ __forceinline__ float sigm(float x)   { return 1.f / (1.f + __expf(-x)); }
__device__ __forceinline__ float tanh_f(float x) { return 1.f - 2.f / (__expf(2.f * x) + 1.f); }

__device__ __forceinline__ uint32_t smem_u32(const void* p) {
    uint32_t a;
    asm("{ .reg .u64 t; cvta.to.shared.u64 t, %1; cvt.u32.u64 %0, t; }" : "=r"(a) : "l"(p));
    return a;
}
__device__ __forceinline__ uint32_t ctarank() {
    uint32_t r; asm("mov.u32 %0, %%cluster_ctarank;" : "=r"(r)); return r;
}

#define MBAR_INIT(addr, cnt) \
    asm volatile("mbarrier.init.shared.b64 [%0], %1;" :: "r"((uint32_t)(addr)), "r"((uint32_t)(cnt)) : "memory")

#define MBAR_ARM_TX(addr, tx) \
    asm volatile("mbarrier.arrive.expect_tx.shared.b64 _, [%0], %1;" :: "r"((uint32_t)(addr)), "r"((uint32_t)(tx)) : "memory")

#define MBAR_WAIT_CLUSTER(addr, ph) do {                                              \
    uint32_t _done = 0;                                                               \
    while (!_done) {                                                                  \
        asm volatile("{\n\t.reg .pred p;\n\t"                                         \
            "mbarrier.try_wait.parity.acquire.cluster.shared::cta.b64 p, [%1], %2;\n\t" \
            "selp.b32 %0, 1, 0, p;\n\t}"                                              \
            : "=r"(_done) : "r"((uint32_t)(addr)), "r"((uint32_t)(ph)) : "memory");   \
    }                                                                                 \
} while (0)

#define ST_ASYNC_F32(raddr, bits, rmbar) \
    asm volatile("st.async.weak.shared::cluster.mbarrier::complete_tx::bytes.b32 [%0], %1, [%2];" \
                 :: "r"(raddr), "r"(bits), "r"(rmbar) : "memory")

__device__ __forceinline__ void splitbf(float v, __nv_bfloat16& hi, __nv_bfloat16& lo) {
    hi = __float2bfloat16(v);
    lo = __float2bfloat16(v - __bfloat162float(hi));
}

// ---- mma.sync / ldmatrix / cp.async (portable sm_80+ path) ----
__device__ __forceinline__ void ldm_x4(uint32_t* r, uint32_t addr) {
    asm volatile("ldmatrix.sync.aligned.m8n8.x4.shared.b16 {%0,%1,%2,%3}, [%4];"
        : "=r"(r[0]), "=r"(r[1]), "=r"(r[2]), "=r"(r[3]) : "r"(addr));
}
__device__ __forceinline__ void ldm_x2(uint32_t* r, uint32_t addr) {
    asm volatile("ldmatrix.sync.aligned.m8n8.x2.shared.b16 {%0,%1}, [%2];"
        : "=r"(r[0]), "=r"(r[1]) : "r"(addr));
}
__device__ __forceinline__ void mma16816(float* d, const uint32_t* a, const uint32_t* b) {
    asm volatile(
        "mma.sync.aligned.m16n8k16.row.col.f32.bf16.bf16.f32 "
        "{%0,%1,%2,%3}, {%4,%5,%6,%7}, {%8,%9}, {%0,%1,%2,%3};"
        : "+f"(d[0]), "+f"(d[1]), "+f"(d[2]), "+f"(d[3])
        : "r"(a[0]), "r"(a[1]), "r"(a[2]), "r"(a[3]), "r"(b[0]), "r"(b[1]));
}
#define CP_ASYNC16(dst, src) \
    asm volatile("cp.async.cg.shared.global [%0], [%1], 16;" :: "r"(dst), "l"(src) : "memory")
#define CP_COMMIT() asm volatile("cp.async.commit_group;" ::: "memory")
#define CP_WAIT(n)  asm volatile("cp.async.wait_group %0;" :: "n"(n) : "memory")

#define STG_BYTES 18432
#define SMEM_FUSED (3 * STG_BYTES)

// shared pipeline prologue macro pieces (identical in both HMMA kernels)
#define HMMA_PREAMBLE(Ah_, Al_, Wh_, Wl_)                                               \
    extern __shared__ __align__(16) char dsm[];                                         \
    uint32_t sb = smem_u32(dsm);                                                        \
    int tid = threadIdx.x, wid = tid >> 5, lane = tid & 31;                             \
    int wm = wid >> 2, nw = wid & 3;                                                    \
    int u0 = blockIdx.x * 32;                                                           \
    int rowBase = blockIdx.y * 64;                                                      \
    int q4 = lane >> 3;                                                                 \
    uint32_t aOff = (uint32_t)((wm * 32 + (q4 & 1) * 8 + (lane & 7)) * 48 + (q4 >> 1) * 16); \
    int ql = lane & 15, q2 = ql >> 3;                                                   \
    uint32_t bOff = (uint32_t)((nw * 8 + (ql & 7)) * 48 + q2 * 16);                     \
    uint32_t aBase[3][2], bBase[3][2];                                                  \
    _Pragma("unroll")                                                                   \
    for (int b = 0; b < 3; b++)                                                         \
        _Pragma("unroll")                                                               \
        for (int s = 0; s < 2; s++) {                                                   \
            aBase[b][s] = sb + (uint32_t)(b * STG_BYTES + s * 3072) + aOff;             \
            bBase[b][s] = sb + (uint32_t)(b * STG_BYTES + 6144 + s * 6144) + bOff;      \
        }                                                                               \
    float acc[2][4][4];                                                                 \
    _Pragma("unroll")                                                                   \
    for (int mt = 0; mt < 2; mt++)                                                      \
        _Pragma("unroll")                                                               \
        for (int g = 0; g < 4; g++)                                                     \
            _Pragma("unroll")                                                           \
            for (int e = 0; e < 4; e++) acc[mt][g][e] = 0.f;

#define H2_ISSUE(kt_, b_, Ah_, Al_, Wh_, Wl_) do { \
    int k0_ = (kt_) * 16; \
    uint32_t stg_ = sb + (uint32_t)((b_) * STG_BYTES); \
    _Pragma("unroll") \
    for (int rep_ = 0; rep_ < 3; rep_++) { \
        int c_ = rep_ * 256 + tid; \
        int slot_ = c_ >> 1, half_ = c_ & 1; \
        uint32_t dst_; const __nv_bfloat16* src_; \
        if (slot_ < 128) { \
            int sel_ = slot_ >> 6, row_ = slot_ & 63; \
            int gr_ = rowBase + row_; if (gr_ >= NN) gr_ = NN - 1; \
            src_ = (sel_ ? (Al_) : (Ah_)) + (size_t)gr_ * 256 + k0_ + half_ * 8; \
            dst_ = stg_ + (uint32_t)(sel_ * 3072 + row_ * 48 + half_ * 16); \
        } else { \
            int s2_ = slot_ - 128; \
            int sel_ = s2_ >> 7, j_ = s2_ & 127; \
            int wrow_ = (j_ >> 5) * 256 + u0 + (j_ & 31); \
            src_ = (sel_ ? (Wl_) : (Wh_)) + (size_t)wrow_ * 256 + k0_ + half_ * 8; \
            dst_ = stg_ + (uint32_t)(6144 + sel_ * 6144 + j_ * 48 + half_ * 16); \
        } \
        CP_ASYNC16(dst_, src_); \
    } \
    CP_COMMIT(); \
} while (0)

#define HMMA_MAINLOOP(Ah_, Al_, Wh_, Wl_)                                               \
    H2_ISSUE(0, 0, Ah_, Al_, Wh_, Wl_);                                                 \
    H2_ISSUE(1, 1, Ah_, Al_, Wh_, Wl_);                                                 \
    _Pragma("unroll 1")                                                                 \
    for (int kt = 0; kt < 16; kt++) {                                                   \
        int buf = kt % 3;                                                               \
        __syncthreads();                                                                \
        if (kt + 2 < 16) { H2_ISSUE(kt + 2, (kt + 2) % 3, Ah_, Al_, Wh_, Wl_); CP_WAIT(2); } \
        else if (kt + 1 < 16) { CP_WAIT(1); }                                           \
        else { CP_WAIT(0); }                                                            \
        uint32_t ahh[2][4], ahl[2][4], bwh[4][2], bwl[4][2];                            \
        _Pragma("unroll")                                                               \
        for (int mt = 0; mt < 2; mt++) {                                                \
            ldm_x4(ahh[mt], aBase[buf][0] + (uint32_t)(mt * 768));                      \
            ldm_x4(ahl[mt], aBase[buf][1] + (uint32_t)(mt * 768));                      \
        }                                                                               \
        _Pragma("unroll")                                                               \
        for (int g = 0; g < 4; g++) {                                                   \
            ldm_x2(bwh[g], bBase[buf][0] + (uint32_t)(g * 1536));                       \
            ldm_x2(bwl[g], bBase[buf][1] + (uint32_t)(g * 1536));                       \
        }                                                                               \
        _Pragma("unroll")                                                               \
        for (int mt = 0; mt < 2; mt++)                                                  \
            _Pragma("unroll")                                                           \
            for (int g = 0; g < 4; g++) {                                               \
                mma16816(acc[mt][g], ahh[mt], bwh[g]);                                  \
                mma16816(acc[mt][g], ahh[mt], bwl[g]);                                  \
                mma16816(acc[mt][g], ahl[mt], bwh[g]);                                  \
            }                                                                           \
    }

// ================= FUSED HMMA step v3 (proven): MMA + gather + cell =================
__global__ __launch_bounds__(256, 3) void fused_hmma_step(
    const __nv_bfloat16* __restrict__ hh, const __nv_bfloat16* __restrict__ hl,
    const float* __restrict__ XW1, const int* __restrict__ edges,
    const float* __restrict__ ew, int t,
    float* __restrict__ houtF, __nv_bfloat16* __restrict__ houth,
    __nv_bfloat16* __restrict__ houtl, float* __restrict__ cbuf)
{
    HMMA_PREAMBLE(hh, hl, g_W1h, g_W1l)
    HMMA_MAINLOOP(hh, hl, g_W1h, g_W1l)

    int uc = u0 + nw * 8 + (lane & 3) * 2;
    #pragma unroll
    for (int mt = 0; mt < 2; mt++) {
        #pragma unroll
        for (int half = 0; half < 2; half++) {
            int r = rowBase + wm * 32 + mt * 16 + (lane >> 2) + half * 8;
            if (r < NN) {
                int eI = edges[r * DD + t];
                float wgt = ew[r * DD + t];
                const float* xr = XW1 + (size_t)eI * 1024;
                float2 xi = *(const float2*)(xr + uc);
                float2 xf = *(const float2*)(xr + 256 + uc);
                float2 xg = *(const float2*)(xr + 512 + uc);
                float2 xo = *(const float2*)(xr + 768 + uc);
                float* cp = cbuf + (size_t)r * 256 + uc;
                float2 cc = *(float2*)cp;
                float hn[2];
                #pragma unroll
                for (int s = 0; s < 2; s++) {
                    int e = half * 2 + s;
                    float vi = acc[mt][0][e] + g_bsum[uc + s]       + wgt * (s ? xi.y : xi.x);
                    float vf = acc[mt][1][e] + g_bsum[256 + uc + s] + wgt * (s ? xf.y : xf.x);
                    float vg = acc[mt][2][e] + g_bsum[512 + uc + s] + wgt * (s ? xg.y : xg.x);
                    float vo = acc[mt][3][e] + g_bsum[768 + uc + s] + wgt * (s ? xo.y : xo.x);
                    float c2 = sigm(vf) * (s ? cc.y : cc.x) + sigm(vi) * tanh_f(vg);
                    if (s) cc.y = c2; else cc.x = c2;
                    hn[s] = sigm(vo) * tanh_f(c2);
                }
                *(float2*)cp = cc;
                *(float2*)(houtF + (size_t)r * 256 + uc) = make_float2(hn[0], hn[1]);
                __nv_bfloat16 a, al, b, bl;
                splitbf(hn[0], a, al);
                splitbf(hn[1], b, bl);
                *(__nv_bfloat162*)(houth + (size_t)r * 256 + uc) = __halves2bfloat162(a, b);
                *(__nv_bfloat162*)(houtl + (size_t)r * 256 + uc) = __halves2bfloat162(al, bl);
            }
        }
    }
}

// ================= HMMA XW kernel: C[M,1024] = (Ah+Al)@(Wh+Wl)^T (+bsum) =================
__global__ __launch_bounds__(256, 3) void hmma_xw_kernel(
    const __nv_bfloat16* __restrict__ Ah, const __nv_bfloat16* __restrict__ Al,
    const __nv_bfloat16* __restrict__ Wh, const __nv_bfloat16* __restrict__ Wl,
    const float* __restrict__ bsum, float* __restrict__ C)
{
    HMMA_PREAMBLE(Ah, Al, Wh, Wl)
    HMMA_MAINLOOP(Ah, Al, Wh, Wl)

    int uc = u0 + nw * 8 + (lane & 3) * 2;
    float2 bb[4];
    #pragma unroll
    for (int g = 0; g < 4; g++) {
        if (bsum != nullptr) {
            bb[g].x = bsum[g * 256 + uc];
            bb[g].y = bsum[g * 256 + uc + 1];
        } else {
            bb[g].x = 0.f; bb[g].y = 0.f;
        }
    }
    #pragma unroll
    for (int mt = 0; mt < 2; mt++) {
        #pragma unroll
        for (int half = 0; half < 2; half++) {
            int r = rowBase + wm * 32 + mt * 16 + (lane >> 2) + half * 8;
            if (r < NN) {
                float* cp = C + (size_t)r * 1024;
                #pragma unroll
                for (int g = 0; g < 4; g++) {
                    float2 o;
                    o.x = acc[mt][g][half * 2 + 0] + bb[g].x;
                    o.y = acc[mt][g][half * 2 + 1] + bb[g].y;
                    *(float2*)(cp + g * 256 + uc) = o;
                }
            }
        }
    }
}

// ---------------- one-time: split weights + node_feats, bias sums ----------------
__global__ void split_w_kernel(const float* __restrict__ Whh1, const float* __restrict__ Wih2,
                               const float* __restrict__ Wih1,
                               const float* __restrict__ bih1, const float* __restrict__ bhh1,
                               const float* __restrict__ bih2, const float* __restrict__ bhh2)
{
    int idx = blockIdx.x * 256 + threadIdx.x;
    if (idx < 1024 * 256) {
        __nv_bfloat16 hi, lo;
        splitbf(Whh1[idx], hi, lo);
        g_W1h[idx] = hi; g_W1l[idx] = lo;
        splitbf(Wih2[idx], hi, lo);
        g_W2h[idx] = hi; g_W2l[idx] = lo;
        splitbf(Wih1[idx], hi, lo);
        g_Wi1h[idx] = hi; g_Wi1l[idx] = lo;
    }
    if (idx < 1024) {
        g_bsum[idx]  = bih1[idx] + bhh1[idx];
        g_bsum2[idx] = bih2[idx] + bhh2[idx];
    }
}

__global__ void split_feats_kernel(const float* __restrict__ nf)
{
    int idx = blockIdx.x * 256 + threadIdx.x;
    if (idx < NN * 256) {
        __nv_bfloat16 hi, lo;
        splitbf(nf[idx], hi, lo);
        g_nfh[idx] = hi; g_nfl[idx] = lo;
    }
}

// ---------------- generic K=256 fp32 GEMM (final projection only) ----------------
#define LOAD_AB(off) do { \
    if (aval) { ra0 = *(const float4*)(Arow + (off)); ra1 = *(const float4*)(Arow + (off) + 4); } \
    else      { ra0 = zf4; ra1 = zf4; } \
    rb0 = *(const float4*)(Wrow + (off)); rb1 = *(const float4*)(Wrow + (off) + 4); \
} while (0)

#define STORE_AB(buf) do { \
    As[buf][lc+0][lr]=ra0.x; As[buf][lc+1][lr]=ra0.y; As[buf][lc+2][lr]=ra0.z; As[buf][lc+3][lr]=ra0.w; \
    As[buf][lc+4][lr]=ra1.x; As[buf][lc+5][lr]=ra1.y; As[buf][lc+6][lr]=ra1.z; As[buf][lc+7][lr]=ra1.w; \
    Bs[buf][lc+0][lr]=rb0.x; Bs[buf][lc+1][lr]=rb0.y; Bs[buf][lc+2][lr]=rb0.z; Bs[buf][lc+3][lr]=rb0.w; \
    Bs[buf][lc+4][lr]=rb1.x; Bs[buf][lc+5][lr]=rb1.y; Bs[buf][lc+6][lr]=rb1.z; Bs[buf][lc+7][lr]=rb1.w; \
} while (0)

__global__ __launch_bounds__(256, 2) void gemm256_kernel(
    const float* __restrict__ A, const float* __restrict__ W,
    float* __restrict__ C, int M, int Nout,
    const float* __restrict__ b1, const float* __restrict__ b2)
{
    __shared__ __align__(16) float As[2][16][128];
    __shared__ __align__(16) float Bs[2][16][128];

    int tid = threadIdx.x;
    int rowBase = blockIdx.y * 128;
    int colBase = blockIdx.x * 128;

    int lr = tid >> 1;
    int lc = (tid & 1) * 8;
    int ar = rowBase + lr;
    const float* Arow = A + (size_t)ar * 256 + lc;
    const float* Wrow = W + (size_t)(colBase + lr) * 256 + lc;
    bool aval = (ar < M);
    float4 zf4 = make_float4(0.f, 0.f, 0.f, 0.f);

    int tm = (tid >> 4) * 8;
    int tn = (tid & 15) * 8;

    unsigned long long acc[8][4];
    #pragma unroll
    for (int i = 0; i < 8; i++)
        #pragma unroll
        for (int j = 0; j < 4; j++) acc[i][j] = 0ull;

    float4 ra0, ra1, rb0, rb1;
    LOAD_AB(0);
    STORE_AB(0);
    __syncthreads();

    #pragma unroll 1
    for (int kt = 0; kt < 16; kt++) {
        int buf = kt & 1;
        if (kt < 15) LOAD_AB((kt + 1) * 16);
        #pragma unroll
        for (int kk = 0; kk < 16; kk++) {
            float4 a0 = *(const float4*)&As[buf][kk][tm];
            float4 a1 = *(const float4*)&As[buf][kk][tm + 4];
            ulonglong2 bq0 = *(const ulonglong2*)&Bs[buf][kk][tn];
            ulonglong2 bq1 = *(const ulonglong2*)&Bs[buf][kk][tn + 4];
            float av[8] = {a0.x, a0.y, a0.z, a0.w, a1.x, a1.y, a1.z, a1.w};
            #pragma unroll
            for (int i = 0; i < 8; i++) {
                unsigned long long aa = pack2f(av[i]);
                FMA2(acc[i][0], aa, bq0.x);
                FMA2(acc[i][1], aa, bq0.y);
                FMA2(acc[i][2], aa, bq1.x);
                FMA2(acc[i][3], aa, bq1.y);
            }
        }
        if (kt < 15) STORE_AB(buf ^ 1);
        __syncthreads();
    }

    float bc[8];
    #pragma unroll
    for (int j = 0; j < 8; j++) {
        int cidx = colBase + tn + j;
        float b = (b1 != nullptr) ? b1[cidx] : 0.f;
        if (b2 != nullptr) b += b2[cidx];
        bc[j] = b;
    }
    #pragma unroll
    for (int i = 0; i < 8; i++) {
        int r = rowBase + tm + i;
        if (r < M) {
            float2 v0 = unpack2f(acc[i][0]);
            float2 v1 = unpack2f(acc[i][1]);
            float2 v2 = unpack2f(acc[i][2]);
            float2 v3 = unpack2f(acc[i][3]);
            float* cp = C + (size_t)r * Nout + colBase + tn;
            *(float4*)cp       = make_float4(v0.x + bc[0], v0.y + bc[1], v1.x + bc[2], v1.y + bc[3]);
            *(float4*)(cp + 4) = make_float4(v2.x + bc[4], v2.y + bc[5], v3.x + bc[6], v3.y + bc[7]);
        }
    }
}

// ---------------- LSTM1 first step (h=c=0) ----------------
__global__ void step0_kernel(const float* __restrict__ XW1, const int* __restrict__ edges,
                             const float* __restrict__ ew,
                             const float* __restrict__ bih1, const float* __restrict__ bhh1,
                             float* __restrict__ h, float* __restrict__ c,
                             __nv_bfloat16* __restrict__ hhi, __nv_bfloat16* __restrict__ hlo)
{
    int idx = blockIdx.x * blockDim.x + threadIdx.x;
    if (idx >= NN * 256) return;
    int n = idx >> 8, j = idx & 255;
    int e = edges[n * DD];
    float w = ew[n * DD];
    const float* x = XW1 + (size_t)e * 1024 + j;
    float ig = bih1[j]       + bhh1[j]       + w * x[0];
    float gg = bih1[512 + j] + bhh1[512 + j] + w * x[512];
    float og = bih1[768 + j] + bhh1[768 + j] + w * x[768];
    float cc = sigm(ig) * tanh_f(gg);
    float hv = sigm(og) * tanh_f(cc);
    h[idx] = hv;
    c[idx] = cc;
    __nv_bfloat16 hi, lo;
    splitbf(hv, hi, lo);
    hhi[idx] = hi;
    hlo[idx] = lo;
}

// ---------------- LSTM2: R12-exact (frozen best-known version) ----------------
__global__ void __cluster_dims__(CL, 1, 1) __launch_bounds__(256, 1)
lstm2_kernel(const float* __restrict__ xw2,
             const float* __restrict__ Whh2,
             float* __restrict__ hs)
{
    __shared__ __align__(16) float h_buf[2][256];
    __shared__ __align__(16) float sg[128];
    __shared__ __align__(8)  unsigned long long mbar[2];

    int tid = threadIdx.x;
    int w = tid >> 5, l = tid & 31;
    int half = l >> 4, sl = l & 15;
    int rank = (int)ctarank();
    int lc0 = w * 16 + half * 8;

    unsigned long long wp[8][8];
    #pragma unroll
    for (int c = 0; c < 8; c++) {
        int lc = lc0 + c;
        int gcol = (lc >> 5) * 256 + rank * 32 + (lc & 31);
        const float* wr = Whh2 + (size_t)gcol * 256;
        #pragma unroll
        for (int j = 0; j < 4; j++) {
            ulonglong2 tq = *(const ulonglong2*)(wr + j * 64 + sl * 4);
            wp[c][2 * j]     = tq.x;
            wp[c][2 * j + 1] = tq.y;
        }
    }

    uint32_t hb = smem_u32(&h_buf[0][0]);
    uint32_t mb = smem_u32(&mbar[0]);
    uint32_t rH[8], rM[8];
    #pragma unroll
    for (int d = 0; d < 8; d++) {
        asm("mapa.shared::cluster.u32 %0, %1, %2;" : "=r"(rH[d]) : "r"(hb), "r"(d));
        asm("mapa.shared::cluster.u32 %0, %1, %2;" : "=r"(rM[d]) : "r"(mb), "r"(d));
    }

    h_buf[0][tid] = 0.f;
    if (tid == 0) {
        MBAR_INIT(mb, 1);
        MBAR_INIT(mb + 8, 1);
        MBAR_ARM_TX(mb + 8, 1024);
    }
    float c_reg = 0.f;
    float xc[4] = {0.f, 0.f, 0.f, 0.f};
    if (tid < 32) {
        #pragma unroll
        for (int q = 0; q < 4; q++) xc[q] = xw2[q * 256 + rank * 32 + tid];
    }
    __syncthreads();
    asm volatile("barrier.cluster.arrive.aligned;" ::: "memory");
    asm volatile("barrier.cluster.wait.aligned;" ::: "memory");

    int p = 0;
    for (int n = 0; n < NN; n++) {
        float xnx[4] = {0.f, 0.f, 0.f, 0.f};
        if (tid < 32 && n + 1 < NN) {
            const float* xp = xw2 + (size_t)(n + 1) * 1024 + rank * 32 + tid;
            #pragma unroll
            for (int q = 0; q < 4; q++) xnx[q] = xp[q * 256];
        }

        const float* hp = &h_buf[p][0];
        unsigned long long acc[8];
        #pragma unroll
        for (int c = 0; c < 8; c++) acc[c] = 0ull;
        #pragma unroll
        for (int j = 0; j < 4; j++) {
            ulonglong2 hv = *(const ulonglong2*)(hp + j * 64 + sl * 4);
            #pragma unroll
            for (int c = 0; c < 8; c++) {
                FMA2(acc[c], hv.x, wp[c][2 * j]);
                FMA2(acc[c], hv.y, wp[c][2 * j + 1]);
            }
        }
        float v[8];
        #pragma unroll
        for (int c = 0; c < 8; c++) { float2 tv = unpack2f(acc[c]); v[c] = tv.x + tv.y; }
        #pragma unroll
        for (int m = 1; m < 16; m <<= 1)
            #pragma unroll
            for (int c = 0; c < 8; c++)
                v[c] += __shfl_xor_sync(0xffffffffu, v[c], m);
        if (sl == 0) {
            *(float4*)&sg[lc0]     = make_float4(v[0], v[1], v[2], v[3]);
            *(float4*)&sg[lc0 + 4] = make_float4(v[4], v[5], v[6], v[7]);
        }
        if (tid == 0) MBAR_ARM_TX(mb + (uint32_t)p * 8, 1024);
        __syncthreads();

        if (tid < 32) {
            float ig = sg[tid]       + xc[0];
            float fg = sg[32 + tid]  + xc[1];
            float gg = sg[64 + tid]  + xc[2];
            float og = sg[96 + tid]  + xc[3];
            c_reg = sigm(fg) * c_reg + sigm(ig) * tanh_f(gg);
            float hn = sigm(og) * tanh_f(c_reg);
            if (n + 1 < NN) {
                uint32_t voff  = (uint32_t)((p ^ 1) * 256 + rank * 32 + tid) * 4u;
                uint32_t mboff = (uint32_t)(p ^ 1) * 8u;
                uint32_t bits  = __float_as_uint(hn);
                #pragma unroll
                for (int d = 0; d < 8; d++)
                    ST_ASYNC_F32(rH[d] + voff, bits, rM[d] + mboff);
            }
            hs[(size_t)n * 256 + rank * 32 + tid] = hn;
            xc[0] = xnx[0]; xc[1] = xnx[1]; xc[2] = xnx[2]; xc[3] = xnx[3];
        }

        if (n + 1 < NN) {
            uint32_t ph = (uint32_t)((n >> 1) & 1);
            MBAR_WAIT_CLUSTER(mb + (uint32_t)(p ^ 1) * 8, ph);
        }
        p ^= 1;
    }
}

// ---------------- launch ----------------
extern "C" void kernel_launch(void* const* d_in, const int* in_sizes, int n_in,
                              void* d_out, int out_size)
{
    const float* node_feats = (const float*)d_in[0];
    const int*   edges      = (const int*)d_in[1];
    const float* ew         = (const float*)d_in[2];
    const float* Wih1       = (const float*)d_in[3];
    const float* Whh1       = (const float*)d_in[4];
    const float* bih1       = (const float*)d_in[5];
    const float* bhh1       = (const float*)d_in[6];
    const float* Wih2       = (const float*)d_in[7];
    const float* Whh2       = (const float*)d_in[8];
    const float* bih2       = (const float*)d_in[9];
    const float* bhh2       = (const float*)d_in[10];
    const float* Wl         = (const float*)d_in[11];
    const float* bl         = (const float*)d_in[12];
    const float* bias       = (const float*)d_in[13];
    float* out = (float*)d_out;

    void *pXW1, *pGates, *pH1, *pHB, *pC1, *pHs, *pHA, *pLA, *pHBs, *pLB, *pNFh, *pNFl;
    void *pW2h, *pW2l, *pWi1h, *pWi1l;
    cudaGetSymbolAddress(&pXW1,   g_XW1);
    cudaGetSymbolAddress(&pGates, g_gates);
    cudaGetSymbolAddress(&pH1,    g_h1);
    cudaGetSymbolAddress(&pHB,    g_hB);
    cudaGetSymbolAddress(&pC1,    g_c1);
    cudaGetSymbolAddress(&pHs,    g_hs);
    cudaGetSymbolAddress(&pHA,    g_hhA);
    cudaGetSymbolAddress(&pLA,    g_hlA);
    cudaGetSymbolAddress(&pHBs,   g_hhB);
    cudaGetSymbolAddress(&pLB,    g_hlB);
    cudaGetSymbolAddress(&pNFh,   g_nfh);
    cudaGetSymbolAddress(&pNFl,   g_nfl);
    cudaGetSymbolAddress(&pW2h,   g_W2h);
    cudaGetSymbolAddress(&pW2l,   g_W2l);
    cudaGetSymbolAddress(&pWi1h,  g_Wi1h);
    cudaGetSymbolAddress(&pWi1l,  g_Wi1l);
    float* XW1   = (float*)pXW1;
    float* gates = (float*)pGates;
    float* h1    = (float*)pH1;
    float* hB    = (float*)pHB;
    float* c1    = (float*)pC1;
    float* hs    = (float*)pHs;
    __nv_bfloat16* hhA = (__nv_bfloat16*)pHA;
    __nv_bfloat16* hlA = (__nv_bfloat16*)pLA;
    __nv_bfloat16* hhB = (__nv_bfloat16*)pHBs;
    __nv_bfloat16* hlB = (__nv_bfloat16*)pLB;
    __nv_bfloat16* nfh = (__nv_bfloat16*)pNFh;
    __nv_bfloat16* nfl = (__nv_bfloat16*)pNFl;
    __nv_bfloat16* W2h = (__nv_bfloat16*)pW2h;
    __nv_bfloat16* W2l = (__nv_bfloat16*)pW2l;
    __nv_bfloat16* Wi1h = (__nv_bfloat16*)pWi1h;
    __nv_bfloat16* Wi1l = (__nv_bfloat16*)pWi1l;

    void* pB2; cudaGetSymbolAddress(&pB2, g_bsum2);
    float* bsum2 = (float*)pB2;

    cudaFuncSetAttribute(fused_hmma_step,
                         cudaFuncAttributeMaxDynamicSharedMemorySize, SMEM_FUSED);
    cudaFuncSetAttribute(hmma_xw_kernel,
                         cudaFuncAttributeMaxDynamicSharedMemorySize, SMEM_FUSED);

    dim3 blk(256);
    int ew_blocks = (NN * 256 + 255) / 256;
    dim3 grid_f(8, 157);

    // one-time splits
    split_w_kernel<<<1024, 256>>>(Whh1, Wih2, Wih1, bih1, bhh1, bih2, bhh2);
    split_feats_kernel<<<ew_blocks, blk>>>(node_feats);
    // XW1 = node_feats @ Wih1^T  (HMMA)
    hmma_xw_kernel<<<grid_f, blk, SMEM_FUSED>>>(nfh, nfl, Wi1h, Wi1l, nullptr, XW1);
    // t = 0
    step0_kernel<<<ew_blocks, blk>>>(XW1, edges, ew, bih1, bhh1, h1, c1, hhA, hlA);
    // t = 1..31: fused HMMA steps
    float* hinF = h1;   float* houtF = hB;
    __nv_bfloat16 *hinH = hhA, *hinL = hlA, *houtH = hhB, *houtL = hlB;
    for (int t = 1; t < DD; t++) {
        fused_hmma_step<<<grid_f, blk, SMEM_FUSED>>>(hinH, hinL, XW1, edges, ew, t,
                                                     houtF, houtH, houtL, c1);
        float* tf = hinF; hinF = houtF; houtF = tf;
        __nv_bfloat16* th = hinH; hinH = houtH; houtH = th;
        __nv_bfloat16* tl = hinL; hinL = houtL; houtL = tl;
    }
    // XW2 = h_agg @ Wih2^T + (bih2+bhh2)  (HMMA; h_agg bf16 split = hinH/hinL)
    hmma_xw_kernel<<<grid_f, blk, SMEM_FUSED>>>(hinH, hinL, W2h, W2l, bsum2, gates);
    // sequential LSTM2 on an 8-CTA cluster (frozen R12 version)
    lstm2_kernel<<<CL, blk>>>(gates, Whh2, hs);
    // out = hs @ Wl^T + bl + bias (fp32, small)
    dim3 grid_fin(2, 79);
    gemm256_kernel<<<grid_fin, blk>>>(hs, Wl, out, NN, 256, bl, bias);
    (void)in_sizes; (void)n_in; (void)out_size;
}